// round 8
// baseline (speedup 1.0000x reference)
#include <cuda_runtime.h>
#include <cstdint>

#define HID 4096
#define NTOK 16384
#define NEXP 64
#define TM 128
#define KC 64
#define NCHUNK (HID / KC)        // 64
#define NCTA (NTOK / TM)         // 128
#define NSTAGE 4

// ---------------- shared memory layout (bytes, dynamic) ----------------
#define SMEM_TMEM_PTR 0
#define MB_FULL(s)  (16 + (s) * 16)
#define MB_EMPTY(s) (24 + (s) * 16)
#define STAGE_BASE 1024
#define XH_OFF 0
#define XL_OFF 16384
#define WH_OFF 32768
#define WL_OFF 40960
#define STAGE_SZ 49152
#define SMEM_BYTES (STAGE_BASE + NSTAGE * STAGE_SZ)   // 197632
// fallback path offsets
#define FB_X 1024
#define FB_W 34048
#define FB_L 50688
// epilogue prob tile (reuses stage 0 after GEMM drained)
#define PN_OFF 1024
#define PN_STRIDE 68

// idesc kind::f16: dtype=F32(1<<4) atype=BF16(1<<7) btype=BF16(1<<10) N=64(8<<17) M=128(8<<24)
#define IDESC 0x8100490u
// SW128 smem descriptor: layout=SW128(2<<61), version=1(1<<46), SBO=64, LBO=1
#define SMEM_DESC_BASE 0x4000404000010000ull

#if defined(__CUDA_ARCH_FEAT_SM103_ALL) || defined(__CUDA_ARCH_FEAT_SM100_ALL) || defined(__CUDA_ARCH_FEAT_SM101_ALL)
#define TCPATH 1
#else
#define TCPATH 0
#endif

__device__ float g_counts[NEXP];
__device__ float g_sumprobs[NEXP];
__device__ float g_entropy;
// W in bf16 hi/lo, chunk-tiled + SW128-swizzled, MMA-ready (8KB per chunk each)
__device__ __align__(1024) uint8_t g_wh[NCHUNK * 8192];
__device__ __align__(1024) uint8_t g_wl[NCHUNK * 8192];

static __device__ __forceinline__ uint32_t swz(uint32_t o) { return o ^ ((o >> 3) & 0x70); }

static __device__ __forceinline__ uint32_t s2u(const void* p) {
    uint32_t a;
    asm("{.reg .u64 t; cvta.to.shared.u64 t, %1; cvt.u32.u64 %0, t;}" : "=r"(a) : "l"(p));
    return a;
}

// split float4 into bf16 hi pair + bf16 lo pair
static __device__ __forceinline__ void split4(float4 v, uint2& hi, uint2& lo) {
    uint32_t h0, h1, l0, l1;
    asm("cvt.rn.bf16x2.f32 %0, %1, %2;" : "=r"(h0) : "f"(v.y), "f"(v.x));
    asm("cvt.rn.bf16x2.f32 %0, %1, %2;" : "=r"(h1) : "f"(v.w), "f"(v.z));
    float fx = __uint_as_float(h0 << 16);
    float fy = __uint_as_float(h0 & 0xffff0000u);
    float fz = __uint_as_float(h1 << 16);
    float fw = __uint_as_float(h1 & 0xffff0000u);
    asm("cvt.rn.bf16x2.f32 %0, %1, %2;" : "=r"(l0) : "f"(v.y - fy), "f"(v.x - fx));
    asm("cvt.rn.bf16x2.f32 %0, %1, %2;" : "=r"(l1) : "f"(v.w - fw), "f"(v.z - fz));
    hi = make_uint2(h0, h1);
    lo = make_uint2(l0, l1);
}

#if TCPATH
static __device__ __forceinline__ uint64_t mk_desc(uint32_t addr) {
    return SMEM_DESC_BASE | (uint64_t)((addr >> 4) & 0x3FFF);
}
static __device__ __forceinline__ void mbar_init(uint32_t mbar, uint32_t cnt) {
    asm volatile("mbarrier.init.shared.b64 [%0], %1;" :: "r"(mbar), "r"(cnt) : "memory");
}
static __device__ __forceinline__ void mbar_arrive(uint32_t mbar) {
    asm volatile("mbarrier.arrive.shared.b64 _, [%0];" :: "r"(mbar) : "memory");
}
static __device__ __forceinline__ void mbar_arrive_tx(uint32_t mbar, uint32_t tx) {
    asm volatile("mbarrier.arrive.expect_tx.shared.b64 _, [%0], %1;"
                 :: "r"(mbar), "r"(tx) : "memory");
}
static __device__ __forceinline__ void mbar_wait(uint32_t mbar, uint32_t parity) {
    asm volatile(
        "{.reg .pred P;\n"
        "W_%=:\n"
        "mbarrier.try_wait.parity.acquire.cta.shared::cta.b64 P, [%0], %1, 0x989680;\n"
        "@!P bra W_%=;}\n" :: "r"(mbar), "r"(parity) : "memory");
}
static __device__ __forceinline__ void bulk_cp(uint32_t dst, const void* src, uint32_t bytes,
                                               uint32_t mbar) {
    asm volatile(
        "cp.async.bulk.shared::cluster.global.mbarrier::complete_tx::bytes [%0], [%1], %2, [%3];"
        :: "r"(dst), "l"(src), "r"(bytes), "r"(mbar) : "memory");
}
static __device__ __forceinline__ void tmem_alloc(uint32_t smem_dst, uint32_t ncols) {
    asm volatile("tcgen05.alloc.cta_group::1.sync.aligned.shared::cta.b32 [%0], %1;"
                 :: "r"(smem_dst), "r"(ncols) : "memory");
}
static __device__ __forceinline__ void tmem_dealloc(uint32_t tmem, uint32_t ncols) {
    asm volatile("tcgen05.relinquish_alloc_permit.cta_group::1.sync.aligned;");
    asm volatile("tcgen05.dealloc.cta_group::1.sync.aligned.b32 %0, %1;" :: "r"(tmem), "r"(ncols));
}
static __device__ __forceinline__ void mma_f16_ss(uint32_t d, uint64_t a, uint64_t b, uint32_t acc) {
    asm volatile(
        "{.reg .pred p; setp.ne.u32 p, %4, 0;\n"
        "tcgen05.mma.cta_group::1.kind::f16 [%0], %1, %2, %3, {%5,%5,%5,%5}, p;}\n"
        :: "r"(d), "l"(a), "l"(b), "r"(IDESC), "r"(acc), "r"(0u) : "memory");
}
static __device__ __forceinline__ void mma_commit(uint32_t mbar) {
    asm volatile(
        "tcgen05.commit.cta_group::1.mbarrier::arrive::one.shared::cluster.b64 [%0];"
        :: "r"(mbar) : "memory");
}
static __device__ __forceinline__ uint32_t elect_one() {
    uint32_t p;
    asm volatile("{.reg .pred P; elect.sync _|P, 0xFFFFFFFF; selp.b32 %0, 1, 0, P;}" : "=r"(p));
    return p;
}
static __device__ __forceinline__ void ldtm32(uint32_t* r, uint32_t a) {
    asm volatile(
        "tcgen05.ld.sync.aligned.32x32b.x32.b32 "
        "{%0,%1,%2,%3,%4,%5,%6,%7,%8,%9,%10,%11,%12,%13,%14,%15,"
        "%16,%17,%18,%19,%20,%21,%22,%23,%24,%25,%26,%27,%28,%29,%30,%31}, [%32];"
        : "=r"(r[0]), "=r"(r[1]), "=r"(r[2]), "=r"(r[3]), "=r"(r[4]), "=r"(r[5]),
          "=r"(r[6]), "=r"(r[7]), "=r"(r[8]), "=r"(r[9]), "=r"(r[10]), "=r"(r[11]),
          "=r"(r[12]), "=r"(r[13]), "=r"(r[14]), "=r"(r[15]), "=r"(r[16]), "=r"(r[17]),
          "=r"(r[18]), "=r"(r[19]), "=r"(r[20]), "=r"(r[21]), "=r"(r[22]), "=r"(r[23]),
          "=r"(r[24]), "=r"(r[25]), "=r"(r[26]), "=r"(r[27]), "=r"(r[28]), "=r"(r[29]),
          "=r"(r[30]), "=r"(r[31])
        : "r"(a));
}
#endif  // TCPATH

// prep: zero stats + convert W -> swizzled bf16 hi/lo chunk tiles
__global__ void router_wprep(const float* __restrict__ W) {
    const int c = blockIdx.x;
    const int tid = threadIdx.x;
    if (c == 0) {
        if (tid < NEXP) { g_counts[tid] = 0.f; g_sumprobs[tid] = 0.f; }
        if (tid == 0) g_entropy = 0.f;
    }
    const int e  = tid >> 2;           // expert row 0..63
    const int kq = (tid & 3) * 16;     // k offset within chunk
    const float* wp = W + (size_t)e * HID + c * KC + kq;
#pragma unroll
    for (int j = 0; j < 4; j++) {
        float4 v = *(const float4*)(wp + 4 * j);
        uint2 hi, lo;
        split4(v, hi, lo);
        uint32_t off = c * 8192 + swz((uint32_t)(e * 128 + (kq + 4 * j) * 2));
        *(uint2*)(g_wh + off) = hi;
        *(uint2*)(g_wl + off) = lo;
    }
}

// no-op spacer so ncu's "-s 5 -c 1" lands on router_main
__global__ void router_nop() {}

__global__ __launch_bounds__(288, 1)
void router_main(const float* __restrict__ x, const float* __restrict__ W,
                 float* __restrict__ out) {
    extern __shared__ char sm[];
    const uint32_t smb = s2u(sm);
    const int tid = threadIdx.x;
    const int lane = tid & 31;
    const int t0 = blockIdx.x * TM;

    // producer x mapping (tid < 256): 8 rows x one k-quad each
    const int q  = tid & 15;
    const int tb = tid >> 4;
    const float* xp = x + (size_t)(t0 + (tb & 15)) * HID + q * 4;

    float l[64];

#if TCPATH
    // ======================= tcgen05 path: 4-stage ring =======================
    if (tid == 0) {
#pragma unroll
        for (int s = 0; s < NSTAGE; s++) {
            mbar_init(smb + MB_FULL(s), 2);     // tid0 (for all producers) + warp8 arrive_tx
            mbar_init(smb + MB_EMPTY(s), 1);
        }
    }
    if ((tid >> 5) == 0) tmem_alloc(smb + SMEM_TMEM_PTR, 64);
    __syncthreads();
    uint32_t tmem;
    asm volatile("ld.shared.b32 %0, [%1];" : "=r"(tmem) : "r"(smb + SMEM_TMEM_PTR));

    if (tid < 256) {
        // ---------------- producers: warps 0-7 (x only, 2-deep prefetch) ----------------
        const int qb = q * 8;
        float4 xr[2][8];
#pragma unroll
        for (int b = 0; b < 2; b++)
#pragma unroll
            for (int r = 0; r < 8; r++)
                xr[b][r] = *(const float4*)(xp + b * KC + (size_t)r * 16 * HID);

#pragma unroll 1
        for (int c = 0; c < NCHUNK; c++) {
            const int s = c & 3;
            const uint32_t st = STAGE_BASE + s * STAGE_SZ;
            mbar_wait(smb + MB_EMPTY(s), 1u ^ ((c >> 2) & 1));

            const int b = c & 1;
#pragma unroll
            for (int r = 0; r < 8; r++) {
                uint2 hi, lo;
                split4(xr[b][r], hi, lo);
                uint32_t off = swz((uint32_t)((tb + r * 16) * 128 + qb));
                *(uint2*)(sm + st + XH_OFF + off) = hi;
                *(uint2*)(sm + st + XL_OFF + off) = lo;
            }
            if (c + 2 < NCHUNK) {
                const int k0 = (c + 2) * KC;
#pragma unroll
                for (int r = 0; r < 8; r++)
                    xr[b][r] = *(const float4*)(xp + k0 + (size_t)r * 16 * HID);
            }
            // barrier over the 256 storing threads, then one fence+arrive
            // (canonical smem->async-proxy handoff: barrier + single fence)
            asm volatile("bar.sync 1, 256;" ::: "memory");
            if (tid == 0) {
                asm volatile("fence.proxy.async.shared::cta;" ::: "memory");
                mbar_arrive(smb + MB_FULL(s));
            }
        }
    } else {
        // ---------------- warp 8: W bulk copies + MMA ----------------
        const uint32_t one = elect_one();
#pragma unroll 1
        for (int c = 0; c < NCHUNK; c++) {
            const int s = c & 3;
            const uint32_t st = STAGE_BASE + s * STAGE_SZ;
            mbar_wait(smb + MB_EMPTY(s), 1u ^ ((c >> 2) & 1));
            if (one) {
                mbar_arrive_tx(smb + MB_FULL(s), 16384);
                bulk_cp(smb + st + WH_OFF, g_wh + (size_t)c * 8192, 8192, smb + MB_FULL(s));
                bulk_cp(smb + st + WL_OFF, g_wl + (size_t)c * 8192, 8192, smb + MB_FULL(s));
            }
            mbar_wait(smb + MB_FULL(s), (c >> 2) & 1);
            if (one) {
                uint64_t axh = mk_desc(smb + st + XH_OFF);
                uint64_t axl = mk_desc(smb + st + XL_OFF);
                uint64_t bwh = mk_desc(smb + st + WH_OFF);
                uint64_t bwl = mk_desc(smb + st + WL_OFF);
#pragma unroll
                for (int k = 0; k < 4; k++) mma_f16_ss(tmem, axh + 2 * k, bwh + 2 * k, (c > 0) | k);
#pragma unroll
                for (int k = 0; k < 4; k++) mma_f16_ss(tmem, axh + 2 * k, bwl + 2 * k, 1);
#pragma unroll
                for (int k = 0; k < 4; k++) mma_f16_ss(tmem, axl + 2 * k, bwh + 2 * k, 1);
                mma_commit(smb + MB_EMPTY(s));
            }
        }
    }

    // drain: each empty barrier completes 16 times; every thread already observed
    // completion #15 before its last pass, so waiting parity 1 here = completion #16.
    __syncthreads();
#pragma unroll
    for (int s = 0; s < NSTAGE; s++) mbar_wait(smb + MB_EMPTY(s), 1);
    asm volatile("tcgen05.fence::after_thread_sync;" ::: "memory");

    if (tid < 128) {
        ldtm32((uint32_t*)l, tmem);
        ldtm32((uint32_t*)l + 32, tmem + 32);
        asm volatile("tcgen05.wait::ld.sync.aligned;" ::: "memory");
    }
#else
    // ======================= fp32 SIMT fallback =======================
    float* x_s = (float*)(sm + FB_X);
    float* w_s = (float*)(sm + FB_W);
    float* l_s = (float*)(sm + FB_L);
    const int tx = tid & 15;
    const int ty = (tid >> 4) & 15;
    const float* wp = W + (size_t)(tb & 15) * HID + q * 4;

    float acc[8][4];
#pragma unroll
    for (int i = 0; i < 8; i++)
#pragma unroll
        for (int j = 0; j < 4; j++) acc[i][j] = 0.f;

    float4 xr[8], wr[4];
    if (tid < 256) {
#pragma unroll
        for (int r = 0; r < 8; r++) xr[r] = *(const float4*)(xp + (size_t)r * 16 * HID);
#pragma unroll
        for (int p = 0; p < 4; p++) wr[p] = *(const float4*)(wp + (size_t)p * 16 * HID);
    }

#pragma unroll 1
    for (int c = 0; c < NCHUNK; c++) {
        if (tid < 256) {
#pragma unroll
            for (int r = 0; r < 8; r++) {
                const float v[4] = {xr[r].x, xr[r].y, xr[r].z, xr[r].w};
#pragma unroll
                for (int j = 0; j < 4; j++) x_s[(q * 4 + j) * (TM + 1) + (tb & 15) + 16 * r] = v[j];
            }
#pragma unroll
            for (int p = 0; p < 4; p++) {
                const float v[4] = {wr[p].x, wr[p].y, wr[p].z, wr[p].w};
#pragma unroll
                for (int j = 0; j < 4; j++) w_s[(q * 4 + j) * (NEXP + 1) + (tb & 15) + 16 * p] = v[j];
            }
        }
        __syncthreads();
        if (tid < 256) {
            if (c + 1 < NCHUNK) {
                const int k0 = (c + 1) * KC;
#pragma unroll
                for (int r = 0; r < 8; r++) xr[r] = *(const float4*)(xp + k0 + (size_t)r * 16 * HID);
#pragma unroll
                for (int p = 0; p < 4; p++) wr[p] = *(const float4*)(wp + k0 + (size_t)p * 16 * HID);
            }
#pragma unroll 8
            for (int kk = 0; kk < KC; kk++) {
                float xf[8], wf[4];
#pragma unroll
                for (int i = 0; i < 8; i++) xf[i] = x_s[kk * (TM + 1) + tx + 16 * i];
#pragma unroll
                for (int j = 0; j < 4; j++) wf[j] = w_s[kk * (NEXP + 1) + ty + 16 * j];
#pragma unroll
                for (int i = 0; i < 8; i++)
#pragma unroll
                    for (int j = 0; j < 4; j++) acc[i][j] = fmaf(xf[i], wf[j], acc[i][j]);
            }
        }
        __syncthreads();
    }
    if (tid < 256) {
#pragma unroll
        for (int i = 0; i < 8; i++)
#pragma unroll
            for (int j = 0; j < 4; j++)
                l_s[(tx + 16 * i) * (NEXP + 1) + ty + 16 * j] = acc[i][j];
    }
    __syncthreads();
    if (tid < 128) {
#pragma unroll
        for (int e = 0; e < NEXP; e++) l[e] = l_s[tid * (NEXP + 1) + e];
    }
#endif

    // ======================= common epilogue =======================
    if (tid < 128) {
        float m = -1e30f, v1 = -1e30f, v2 = -1e30f;
        int i1 = 0, i2 = 0;
#pragma unroll
        for (int e = 0; e < NEXP; e++) {
            float v = l[e];
            m = fmaxf(m, v);
            if (v > v1)      { v2 = v1; i2 = i1; v1 = v; i1 = e; }
            else if (v > v2) { v2 = v;  i2 = e; }
        }
        float s = 0.f, A = 0.f;
#pragma unroll
        for (int e = 0; e < NEXP; e++) {
            float d = l[e] - m;
            float p = __expf(d);
            l[e] = p;
            s += p;
            A = fmaf(d, p, A);
        }
        const float inv = 1.0f / s;

        const float p1 = __expf(v1 - m), p2 = __expf(v2 - m);
        const float iw = 1.0f / (p1 + p2);
        const int token = t0 + tid;
        out[2 * token]                = (float)i1;
        out[2 * token + 1]            = (float)i2;
        out[2 * NTOK + 2 * token]     = p1 * iw;
        out[2 * NTOK + 2 * token + 1] = p2 * iw;
        atomicAdd(&g_counts[i1], 1.0f);
        atomicAdd(&g_counts[i2], 1.0f);

        float ent = __logf(s) - A * inv;
#pragma unroll
        for (int o = 16; o > 0; o >>= 1) ent += __shfl_xor_sync(0xffffffffu, ent, o);
        if (lane == 0) atomicAdd(&g_entropy, ent);

        float* pn = (float*)(sm + PN_OFF) + tid * PN_STRIDE;
#pragma unroll
        for (int e4 = 0; e4 < 16; e4++) {
            float4 v;
            v.x = l[4 * e4 + 0] * inv;
            v.y = l[4 * e4 + 1] * inv;
            v.z = l[4 * e4 + 2] * inv;
            v.w = l[4 * e4 + 3] * inv;
            *(float4*)(pn + 4 * e4) = v;
        }
    }
    __syncthreads();

    if (tid < 256) {
        const int e = tid & 63;
        const int g = tid >> 6;
        const float* pn = (float*)(sm + PN_OFF);
        float ps = 0.f;
#pragma unroll 8
        for (int t = g * 32; t < g * 32 + 32; t++)
            ps += pn[t * PN_STRIDE + e];
        atomicAdd(&g_sumprobs[e], ps);
    }
#if TCPATH
    __syncthreads();
    if ((tid >> 5) == 0) tmem_dealloc(tmem, 64);
#endif
}

__global__ void router_finalize(float* __restrict__ out) {
    int tid = threadIdx.x;
    if (tid < NEXP) {
        out[2 * NTOK * 2 + tid]        = g_counts[tid];
        out[2 * NTOK * 2 + NEXP + tid] = g_sumprobs[tid] * (1.0f / (float)NTOK);
    }
    __syncthreads();
    if (tid == 0) {
        out[2 * NTOK * 2 + 2 * NEXP] = g_entropy * (1.0f / (float)NTOK);
        float c[NEXP];
        for (int i = 0; i < NEXP; i++) c[i] = g_counts[i];
        for (int i = 1; i < NEXP; i++) {
            float v = c[i]; int j = i - 1;
            while (j >= 0 && c[j] > v) { c[j + 1] = c[j]; j--; }
            c[j + 1] = v;
        }
        float num = 0.f, tot = 0.f;
        for (int i = 0; i < NEXP; i++) {
            num = fmaf(2.0f * (float)(i + 1) - (float)NEXP - 1.0f, c[i], num);
            tot += c[i];
        }
        out[2 * NTOK * 2 + 2 * NEXP + 1] = num / ((float)NEXP * tot + 1e-10f);
    }
}

extern "C" void kernel_launch(void* const* d_in, const int* in_sizes, int n_in,
                              void* d_out, int out_size) {
    const float* x = (const float*)d_in[0];
    const float* W = (const float*)d_in[1];
    float* out = (float*)d_out;

    cudaFuncSetAttribute(router_main, cudaFuncAttributeMaxDynamicSharedMemorySize, SMEM_BYTES);

    router_wprep<<<NCHUNK, 256>>>(W);
    router_nop<<<1, 32>>>();
    router_nop<<<1, 32>>>();
    router_main<<<NCTA, 288, SMEM_BYTES>>>(x, W, out);
    router_finalize<<<1, 64>>>(out);
}

// round 9
// speedup vs baseline: 1.0222x; 1.0222x over previous
#include <cuda_runtime.h>
#include <cstdint>

#define HID 4096
#define NTOK 16384
#define NEXP 64
#define TM 128
#define KC 64
#define NCHUNK (HID / KC)        // 64
#define NCTA (NTOK / TM)         // 128
#define NSTAGE 4

// ---------------- shared memory layout (bytes, dynamic) ----------------
#define SMEM_TMEM_PTR 0
#define MB_FULL(s)  (16 + (s) * 16)
#define MB_EMPTY(s) (24 + (s) * 16)
#define STAGE_BASE 1024
#define XH_OFF 0
#define XL_OFF 16384
#define WH_OFF 32768
#define WL_OFF 40960
#define STAGE_SZ 49152
#define SMEM_BYTES (STAGE_BASE + NSTAGE * STAGE_SZ)   // 197632
// fallback path offsets
#define FB_X 1024
#define FB_W 34048
#define FB_L 50688
// epilogue prob tile (reuses stage 0 after GEMM drained)
#define PN_OFF 1024
#define PN_STRIDE 68

// idesc kind::f16: dtype=F32(1<<4) atype=BF16(1<<7) btype=BF16(1<<10) N=64(8<<17) M=128(8<<24)
#define IDESC 0x8100490u
// SW128 smem descriptor: layout=SW128(2<<61), version=1(1<<46), SBO=64, LBO=1
#define SMEM_DESC_BASE 0x4000404000010000ull

#if defined(__CUDA_ARCH_FEAT_SM103_ALL) || defined(__CUDA_ARCH_FEAT_SM100_ALL) || defined(__CUDA_ARCH_FEAT_SM101_ALL)
#define TCPATH 1
#else
#define TCPATH 0
#endif

__device__ float g_counts[NEXP];
__device__ float g_sumprobs[NEXP];
__device__ float g_entropy;
// W in bf16 hi/lo, chunk-tiled + SW128-swizzled, MMA-ready (8KB per chunk each)
__device__ __align__(1024) uint8_t g_wh[NCHUNK * 8192];
__device__ __align__(1024) uint8_t g_wl[NCHUNK * 8192];

static __device__ __forceinline__ uint32_t swz(uint32_t o) { return o ^ ((o >> 3) & 0x70); }

static __device__ __forceinline__ uint32_t s2u(const void* p) {
    uint32_t a;
    asm("{.reg .u64 t; cvta.to.shared.u64 t, %1; cvt.u32.u64 %0, t;}" : "=r"(a) : "l"(p));
    return a;
}

// split float4 into bf16 hi pair + bf16 lo pair
static __device__ __forceinline__ void split4(float4 v, uint2& hi, uint2& lo) {
    uint32_t h0, h1, l0, l1;
    asm("cvt.rn.bf16x2.f32 %0, %1, %2;" : "=r"(h0) : "f"(v.y), "f"(v.x));
    asm("cvt.rn.bf16x2.f32 %0, %1, %2;" : "=r"(h1) : "f"(v.w), "f"(v.z));
    float fx = __uint_as_float(h0 << 16);
    float fy = __uint_as_float(h0 & 0xffff0000u);
    float fz = __uint_as_float(h1 << 16);
    float fw = __uint_as_float(h1 & 0xffff0000u);
    asm("cvt.rn.bf16x2.f32 %0, %1, %2;" : "=r"(l0) : "f"(v.y - fy), "f"(v.x - fx));
    asm("cvt.rn.bf16x2.f32 %0, %1, %2;" : "=r"(l1) : "f"(v.w - fw), "f"(v.z - fz));
    hi = make_uint2(h0, h1);
    lo = make_uint2(l0, l1);
}

#if TCPATH
static __device__ __forceinline__ uint64_t mk_desc(uint32_t addr) {
    return SMEM_DESC_BASE | (uint64_t)((addr >> 4) & 0x3FFF);
}
static __device__ __forceinline__ void mbar_init(uint32_t mbar, uint32_t cnt) {
    asm volatile("mbarrier.init.shared.b64 [%0], %1;" :: "r"(mbar), "r"(cnt) : "memory");
}
static __device__ __forceinline__ void mbar_arrive(uint32_t mbar) {
    asm volatile("mbarrier.arrive.shared.b64 _, [%0];" :: "r"(mbar) : "memory");
}
static __device__ __forceinline__ void mbar_arrive_tx(uint32_t mbar, uint32_t tx) {
    asm volatile("mbarrier.arrive.expect_tx.shared.b64 _, [%0], %1;"
                 :: "r"(mbar), "r"(tx) : "memory");
}
static __device__ __forceinline__ void mbar_wait(uint32_t mbar, uint32_t parity) {
    asm volatile(
        "{.reg .pred P;\n"
        "W_%=:\n"
        "mbarrier.try_wait.parity.acquire.cta.shared::cta.b64 P, [%0], %1, 0x989680;\n"
        "@!P bra W_%=;}\n" :: "r"(mbar), "r"(parity) : "memory");
}
static __device__ __forceinline__ void bulk_cp(uint32_t dst, const void* src, uint32_t bytes,
                                               uint32_t mbar) {
    asm volatile(
        "cp.async.bulk.shared::cluster.global.mbarrier::complete_tx::bytes [%0], [%1], %2, [%3];"
        :: "r"(dst), "l"(src), "r"(bytes), "r"(mbar) : "memory");
}
static __device__ __forceinline__ void tmem_alloc(uint32_t smem_dst, uint32_t ncols) {
    asm volatile("tcgen05.alloc.cta_group::1.sync.aligned.shared::cta.b32 [%0], %1;"
                 :: "r"(smem_dst), "r"(ncols) : "memory");
}
static __device__ __forceinline__ void tmem_dealloc(uint32_t tmem, uint32_t ncols) {
    asm volatile("tcgen05.relinquish_alloc_permit.cta_group::1.sync.aligned;");
    asm volatile("tcgen05.dealloc.cta_group::1.sync.aligned.b32 %0, %1;" :: "r"(tmem), "r"(ncols));
}
static __device__ __forceinline__ void mma_f16_ss(uint32_t d, uint64_t a, uint64_t b, uint32_t acc) {
    asm volatile(
        "{.reg .pred p; setp.ne.u32 p, %4, 0;\n"
        "tcgen05.mma.cta_group::1.kind::f16 [%0], %1, %2, %3, {%5,%5,%5,%5}, p;}\n"
        :: "r"(d), "l"(a), "l"(b), "r"(IDESC), "r"(acc), "r"(0u) : "memory");
}
static __device__ __forceinline__ void mma_commit(uint32_t mbar) {
    asm volatile(
        "tcgen05.commit.cta_group::1.mbarrier::arrive::one.shared::cluster.b64 [%0];"
        :: "r"(mbar) : "memory");
}
static __device__ __forceinline__ uint32_t elect_one() {
    uint32_t p;
    asm volatile("{.reg .pred P; elect.sync _|P, 0xFFFFFFFF; selp.b32 %0, 1, 0, P;}" : "=r"(p));
    return p;
}
static __device__ __forceinline__ void ldtm32(uint32_t* r, uint32_t a) {
    asm volatile(
        "tcgen05.ld.sync.aligned.32x32b.x32.b32 "
        "{%0,%1,%2,%3,%4,%5,%6,%7,%8,%9,%10,%11,%12,%13,%14,%15,"
        "%16,%17,%18,%19,%20,%21,%22,%23,%24,%25,%26,%27,%28,%29,%30,%31}, [%32];"
        : "=r"(r[0]), "=r"(r[1]), "=r"(r[2]), "=r"(r[3]), "=r"(r[4]), "=r"(r[5]),
          "=r"(r[6]), "=r"(r[7]), "=r"(r[8]), "=r"(r[9]), "=r"(r[10]), "=r"(r[11]),
          "=r"(r[12]), "=r"(r[13]), "=r"(r[14]), "=r"(r[15]), "=r"(r[16]), "=r"(r[17]),
          "=r"(r[18]), "=r"(r[19]), "=r"(r[20]), "=r"(r[21]), "=r"(r[22]), "=r"(r[23]),
          "=r"(r[24]), "=r"(r[25]), "=r"(r[26]), "=r"(r[27]), "=r"(r[28]), "=r"(r[29]),
          "=r"(r[30]), "=r"(r[31])
        : "r"(a));
}
#endif  // TCPATH

// prep: zero stats + convert W -> swizzled bf16 hi/lo chunk tiles
__global__ void router_wprep(const float* __restrict__ W) {
    const int c = blockIdx.x;
    const int tid = threadIdx.x;
    if (c == 0) {
        if (tid < NEXP) { g_counts[tid] = 0.f; g_sumprobs[tid] = 0.f; }
        if (tid == 0) g_entropy = 0.f;
    }
    const int e  = tid >> 2;           // expert row 0..63
    const int kq = (tid & 3) * 16;     // k offset within chunk
    const float* wp = W + (size_t)e * HID + c * KC + kq;
#pragma unroll
    for (int j = 0; j < 4; j++) {
        float4 v = *(const float4*)(wp + 4 * j);
        uint2 hi, lo;
        split4(v, hi, lo);
        uint32_t off = c * 8192 + swz((uint32_t)(e * 128 + (kq + 4 * j) * 2));
        *(uint2*)(g_wh + off) = hi;
        *(uint2*)(g_wl + off) = lo;
    }
}

__global__ __launch_bounds__(288, 1)
void router_main(const float* __restrict__ x, const float* __restrict__ W,
                 float* __restrict__ out) {
    extern __shared__ char sm[];
    const uint32_t smb = s2u(sm);
    const int tid = threadIdx.x;
    const int lane = tid & 31;
    const int t0 = blockIdx.x * TM;

    // producer x mapping (tid < 256): 8 rows x one k-quad each
    const int q  = tid & 15;
    const int tb = tid >> 4;
    const float* xp = x + (size_t)(t0 + (tb & 15)) * HID + q * 4;

    float l[64];

#if TCPATH
    // ======================= tcgen05 path: 4-stage ring =======================
    if (tid == 0) {
#pragma unroll
        for (int s = 0; s < NSTAGE; s++) {
            mbar_init(smb + MB_FULL(s), 2);     // tid0 (for all producers) + warp8 arrive_tx
            mbar_init(smb + MB_EMPTY(s), 1);
        }
    }
    if ((tid >> 5) == 0) tmem_alloc(smb + SMEM_TMEM_PTR, 64);
    __syncthreads();
    uint32_t tmem;
    asm volatile("ld.shared.b32 %0, [%1];" : "=r"(tmem) : "r"(smb + SMEM_TMEM_PTR));

    if (tid < 256) {
        // ---------------- producers: warps 0-7 (x only, 2-deep prefetch) ----------------
        const int qb = q * 8;
        float4 xr[2][8];
#pragma unroll
        for (int b = 0; b < 2; b++)
#pragma unroll
            for (int r = 0; r < 8; r++)
                xr[b][r] = *(const float4*)(xp + b * KC + (size_t)r * 16 * HID);

#pragma unroll 1
        for (int c = 0; c < NCHUNK; c++) {
            const int s = c & 3;
            const uint32_t st = STAGE_BASE + s * STAGE_SZ;
            // per-warp empty wait (commit completion observed by lane0; warp
            // execution order covers the stage-reuse WAR for other lanes)
            if (lane == 0) mbar_wait(smb + MB_EMPTY(s), 1u ^ ((c >> 2) & 1));
            __syncwarp();

            const int b = c & 1;
#pragma unroll
            for (int r = 0; r < 8; r++) {
                uint2 hi, lo;
                split4(xr[b][r], hi, lo);
                uint32_t off = swz((uint32_t)((tb + r * 16) * 128 + qb));
                *(uint2*)(sm + st + XH_OFF + off) = hi;
                *(uint2*)(sm + st + XL_OFF + off) = lo;
            }
            if (c + 2 < NCHUNK) {
                const int k0 = (c + 2) * KC;
#pragma unroll
                for (int r = 0; r < 8; r++)
                    xr[b][r] = *(const float4*)(xp + k0 + (size_t)r * 16 * HID);
            }
            // barrier over the 256 storing threads, then one fence+arrive
            asm volatile("bar.sync 1, 256;" ::: "memory");
            if (tid == 0) {
                asm volatile("fence.proxy.async.shared::cta;" ::: "memory");
                mbar_arrive(smb + MB_FULL(s));
            }
        }
    } else {
        // ---------------- warp 8: 2-ahead W bulk copies + MMA ----------------
        const uint32_t one = elect_one();
        // prologue: stages 0,1 are fresh -> issue their W copies immediately
        if (one) {
            mbar_arrive_tx(smb + MB_FULL(0), 16384);
            bulk_cp(smb + STAGE_BASE + 0 * STAGE_SZ + WH_OFF, g_wh + 0 * 8192, 8192, smb + MB_FULL(0));
            bulk_cp(smb + STAGE_BASE + 0 * STAGE_SZ + WL_OFF, g_wl + 0 * 8192, 8192, smb + MB_FULL(0));
            mbar_arrive_tx(smb + MB_FULL(1), 16384);
            bulk_cp(smb + STAGE_BASE + 1 * STAGE_SZ + WH_OFF, g_wh + 1 * 8192, 8192, smb + MB_FULL(1));
            bulk_cp(smb + STAGE_BASE + 1 * STAGE_SZ + WL_OFF, g_wl + 1 * 8192, 8192, smb + MB_FULL(1));
        }
#pragma unroll 1
        for (int c = 0; c < NCHUNK; c++) {
            const int s = c & 3;
            const uint32_t st = STAGE_BASE + s * STAGE_SZ;
            // issue W bulk for chunk c+2 (its empty flipped at commit(c-2))
            if (c + 2 < NCHUNK) {
                const int u = c + 2;
                const int s2 = u & 3;
                mbar_wait(smb + MB_EMPTY(s2), 1u ^ ((u >> 2) & 1));
                if (one) {
                    mbar_arrive_tx(smb + MB_FULL(s2), 16384);
                    bulk_cp(smb + STAGE_BASE + s2 * STAGE_SZ + WH_OFF,
                            g_wh + (size_t)u * 8192, 8192, smb + MB_FULL(s2));
                    bulk_cp(smb + STAGE_BASE + s2 * STAGE_SZ + WL_OFF,
                            g_wl + (size_t)u * 8192, 8192, smb + MB_FULL(s2));
                }
            }
            mbar_wait(smb + MB_FULL(s), (c >> 2) & 1);
            if (one) {
                uint64_t axh = mk_desc(smb + st + XH_OFF);
                uint64_t axl = mk_desc(smb + st + XL_OFF);
                uint64_t bwh = mk_desc(smb + st + WH_OFF);
                uint64_t bwl = mk_desc(smb + st + WL_OFF);
#pragma unroll
                for (int k = 0; k < 4; k++) mma_f16_ss(tmem, axh + 2 * k, bwh + 2 * k, (c > 0) | k);
#pragma unroll
                for (int k = 0; k < 4; k++) mma_f16_ss(tmem, axh + 2 * k, bwl + 2 * k, 1);
#pragma unroll
                for (int k = 0; k < 4; k++) mma_f16_ss(tmem, axl + 2 * k, bwh + 2 * k, 1);
                mma_commit(smb + MB_EMPTY(s));
            }
        }
    }

    // drain: each empty barrier completes 16 times; waiting parity 1 here
    // corresponds to completion #16 (the final commit of each stage).
    __syncthreads();
#pragma unroll
    for (int s = 0; s < NSTAGE; s++) mbar_wait(smb + MB_EMPTY(s), 1);
    asm volatile("tcgen05.fence::after_thread_sync;" ::: "memory");

    if (tid < 128) {
        ldtm32((uint32_t*)l, tmem);
        ldtm32((uint32_t*)l + 32, tmem + 32);
        asm volatile("tcgen05.wait::ld.sync.aligned;" ::: "memory");
    }
#else
    // ======================= fp32 SIMT fallback =======================
    float* x_s = (float*)(sm + FB_X);
    float* w_s = (float*)(sm + FB_W);
    float* l_s = (float*)(sm + FB_L);
    const int tx = tid & 15;
    const int ty = (tid >> 4) & 15;
    const float* wp = W + (size_t)(tb & 15) * HID + q * 4;

    float acc[8][4];
#pragma unroll
    for (int i = 0; i < 8; i++)
#pragma unroll
        for (int j = 0; j < 4; j++) acc[i][j] = 0.f;

    float4 xr[8], wr[4];
    if (tid < 256) {
#pragma unroll
        for (int r = 0; r < 8; r++) xr[r] = *(const float4*)(xp + (size_t)r * 16 * HID);
#pragma unroll
        for (int p = 0; p < 4; p++) wr[p] = *(const float4*)(wp + (size_t)p * 16 * HID);
    }

#pragma unroll 1
    for (int c = 0; c < NCHUNK; c++) {
        if (tid < 256) {
#pragma unroll
            for (int r = 0; r < 8; r++) {
                const float v[4] = {xr[r].x, xr[r].y, xr[r].z, xr[r].w};
#pragma unroll
                for (int j = 0; j < 4; j++) x_s[(q * 4 + j) * (TM + 1) + (tb & 15) + 16 * r] = v[j];
            }
#pragma unroll
            for (int p = 0; p < 4; p++) {
                const float v[4] = {wr[p].x, wr[p].y, wr[p].z, wr[p].w};
#pragma unroll
                for (int j = 0; j < 4; j++) w_s[(q * 4 + j) * (NEXP + 1) + (tb & 15) + 16 * p] = v[j];
            }
        }
        __syncthreads();
        if (tid < 256) {
            if (c + 1 < NCHUNK) {
                const int k0 = (c + 1) * KC;
#pragma unroll
                for (int r = 0; r < 8; r++) xr[r] = *(const float4*)(xp + k0 + (size_t)r * 16 * HID);
#pragma unroll
                for (int p = 0; p < 4; p++) wr[p] = *(const float4*)(wp + k0 + (size_t)p * 16 * HID);
            }
#pragma unroll 8
            for (int kk = 0; kk < KC; kk++) {
                float xf[8], wf[4];
#pragma unroll
                for (int i = 0; i < 8; i++) xf[i] = x_s[kk * (TM + 1) + tx + 16 * i];
#pragma unroll
                for (int j = 0; j < 4; j++) wf[j] = w_s[kk * (NEXP + 1) + ty + 16 * j];
#pragma unroll
                for (int i = 0; i < 8; i++)
#pragma unroll
                    for (int j = 0; j < 4; j++) acc[i][j] = fmaf(xf[i], wf[j], acc[i][j]);
            }
        }
        __syncthreads();
    }
    if (tid < 256) {
#pragma unroll
        for (int i = 0; i < 8; i++)
#pragma unroll
            for (int j = 0; j < 4; j++)
                l_s[(tx + 16 * i) * (NEXP + 1) + ty + 16 * j] = acc[i][j];
    }
    __syncthreads();
    if (tid < 128) {
#pragma unroll
        for (int e = 0; e < NEXP; e++) l[e] = l_s[tid * (NEXP + 1) + e];
    }
#endif

    // ======================= common epilogue =======================
    if (tid < 128) {
        float m = -1e30f, v1 = -1e30f, v2 = -1e30f;
        int i1 = 0, i2 = 0;
#pragma unroll
        for (int e = 0; e < NEXP; e++) {
            float v = l[e];
            m = fmaxf(m, v);
            if (v > v1)      { v2 = v1; i2 = i1; v1 = v; i1 = e; }
            else if (v > v2) { v2 = v;  i2 = e; }
        }
        float s = 0.f, A = 0.f;
#pragma unroll
        for (int e = 0; e < NEXP; e++) {
            float d = l[e] - m;
            float p = __expf(d);
            l[e] = p;
            s += p;
            A = fmaf(d, p, A);
        }
        const float inv = 1.0f / s;

        const float p1 = __expf(v1 - m), p2 = __expf(v2 - m);
        const float iw = 1.0f / (p1 + p2);
        const int token = t0 + tid;
        out[2 * token]                = (float)i1;
        out[2 * token + 1]            = (float)i2;
        out[2 * NTOK + 2 * token]     = p1 * iw;
        out[2 * NTOK + 2 * token + 1] = p2 * iw;
        atomicAdd(&g_counts[i1], 1.0f);
        atomicAdd(&g_counts[i2], 1.0f);

        float ent = __logf(s) - A * inv;
#pragma unroll
        for (int o = 16; o > 0; o >>= 1) ent += __shfl_xor_sync(0xffffffffu, ent, o);
        if (lane == 0) atomicAdd(&g_entropy, ent);

        float* pn = (float*)(sm + PN_OFF) + tid * PN_STRIDE;
#pragma unroll
        for (int e4 = 0; e4 < 16; e4++) {
            float4 v;
            v.x = l[4 * e4 + 0] * inv;
            v.y = l[4 * e4 + 1] * inv;
            v.z = l[4 * e4 + 2] * inv;
            v.w = l[4 * e4 + 3] * inv;
            *(float4*)(pn + 4 * e4) = v;
        }
    }
    __syncthreads();

    if (tid < 256) {
        const int e = tid & 63;
        const int g = tid >> 6;
        const float* pn = (float*)(sm + PN_OFF);
        float ps = 0.f;
#pragma unroll 8
        for (int t = g * 32; t < g * 32 + 32; t++)
            ps += pn[t * PN_STRIDE + e];
        atomicAdd(&g_sumprobs[e], ps);
    }
#if TCPATH
    __syncthreads();
    if ((tid >> 5) == 0) tmem_dealloc(tmem, 64);
#endif
}

__global__ void router_finalize(float* __restrict__ out) {
    int tid = threadIdx.x;
    if (tid < NEXP) {
        out[2 * NTOK * 2 + tid]        = g_counts[tid];
        out[2 * NTOK * 2 + NEXP + tid] = g_sumprobs[tid] * (1.0f / (float)NTOK);
    }
    __syncthreads();
    if (tid == 0) {
        out[2 * NTOK * 2 + 2 * NEXP] = g_entropy * (1.0f / (float)NTOK);
        float c[NEXP];
        for (int i = 0; i < NEXP; i++) c[i] = g_counts[i];
        for (int i = 1; i < NEXP; i++) {
            float v = c[i]; int j = i - 1;
            while (j >= 0 && c[j] > v) { c[j + 1] = c[j]; j--; }
            c[j + 1] = v;
        }
        float num = 0.f, tot = 0.f;
        for (int i = 0; i < NEXP; i++) {
            num = fmaf(2.0f * (float)(i + 1) - (float)NEXP - 1.0f, c[i], num);
            tot += c[i];
        }
        out[2 * NTOK * 2 + 2 * NEXP + 1] = num / ((float)NEXP * tot + 1e-10f);
    }
}

extern "C" void kernel_launch(void* const* d_in, const int* in_sizes, int n_in,
                              void* d_out, int out_size) {
    const float* x = (const float*)d_in[0];
    const float* W = (const float*)d_in[1];
    float* out = (float*)d_out;

    cudaFuncSetAttribute(router_main, cudaFuncAttributeMaxDynamicSharedMemorySize, SMEM_BYTES);

    router_wprep<<<NCHUNK, 256>>>(W);
    router_main<<<NCTA, 288, SMEM_BYTES>>>(x, W, out);
    router_finalize<<<1, 64>>>(out);
}

// round 10
// speedup vs baseline: 1.2839x; 1.2561x over previous
#include <cuda_runtime.h>
#include <cstdint>

#define HID 4096
#define NTOK 16384
#define NEXP 64
#define TM 128
#define KC 128
#define NCHUNK (HID / KC)        // 32
#define NCTA (NTOK / TM)         // 128
#define NSTAGE 2

// ---------------- shared memory layout (bytes, dynamic) ----------------
#define SMEM_TMEM_PTR 0
#define MB_FULL(s)  (16 + (s) * 16)
#define MB_EMPTY(s) (24 + (s) * 16)
#define STAGE_BASE 1024
#define XH_OFF 0
#define XL_OFF 32768
#define WH_OFF 65536
#define WL_OFF 81920
#define STAGE_SZ 98304
#define SMEM_BYTES (STAGE_BASE + NSTAGE * STAGE_SZ)   // 197632
// fallback path offsets (fallback uses its own 64-wide chunks)
#define FB_X 1024
#define FB_W 34048
#define FB_L 50688
// epilogue prob tile (reuses stage 0 after GEMM drained)
#define PN_OFF 1024
#define PN_STRIDE 68

// idesc kind::f16: dtype=F32(1<<4) atype=BF16(1<<7) btype=BF16(1<<10) N=64(8<<17) M=128(8<<24)
#define IDESC 0x8100490u
// SW128 smem descriptor: layout=SW128(2<<61), version=1(1<<46), SBO=64, LBO=1
#define SMEM_DESC_BASE 0x4000404000010000ull

#if defined(__CUDA_ARCH_FEAT_SM103_ALL) || defined(__CUDA_ARCH_FEAT_SM100_ALL) || defined(__CUDA_ARCH_FEAT_SM101_ALL)
#define TCPATH 1
#else
#define TCPATH 0
#endif

__device__ float g_counts[NEXP];
__device__ float g_sumprobs[NEXP];
__device__ float g_entropy;
// W in bf16 hi/lo, chunk-tiled (16KB per chunk), blocked-atom SW128, MMA-ready
__device__ __align__(1024) uint8_t g_wh[NCHUNK * 16384];
__device__ __align__(1024) uint8_t g_wl[NCHUNK * 16384];

static __device__ __forceinline__ uint32_t swz(uint32_t o) { return o ^ ((o >> 3) & 0x70); }

static __device__ __forceinline__ uint32_t s2u(const void* p) {
    uint32_t a;
    asm("{.reg .u64 t; cvta.to.shared.u64 t, %1; cvt.u32.u64 %0, t;}" : "=r"(a) : "l"(p));
    return a;
}

// split float4 into bf16 hi pair + bf16 lo pair
static __device__ __forceinline__ void split4(float4 v, uint2& hi, uint2& lo) {
    uint32_t h0, h1, l0, l1;
    asm("cvt.rn.bf16x2.f32 %0, %1, %2;" : "=r"(h0) : "f"(v.y), "f"(v.x));
    asm("cvt.rn.bf16x2.f32 %0, %1, %2;" : "=r"(h1) : "f"(v.w), "f"(v.z));
    float fx = __uint_as_float(h0 << 16);
    float fy = __uint_as_float(h0 & 0xffff0000u);
    float fz = __uint_as_float(h1 << 16);
    float fw = __uint_as_float(h1 & 0xffff0000u);
    asm("cvt.rn.bf16x2.f32 %0, %1, %2;" : "=r"(l0) : "f"(v.y - fy), "f"(v.x - fx));
    asm("cvt.rn.bf16x2.f32 %0, %1, %2;" : "=r"(l1) : "f"(v.w - fw), "f"(v.z - fz));
    hi = make_uint2(h0, h1);
    lo = make_uint2(l0, l1);
}

#if TCPATH
static __device__ __forceinline__ uint64_t mk_desc(uint32_t addr) {
    return SMEM_DESC_BASE | (uint64_t)((addr >> 4) & 0x3FFF);
}
static __device__ __forceinline__ void mbar_init(uint32_t mbar, uint32_t cnt) {
    asm volatile("mbarrier.init.shared.b64 [%0], %1;" :: "r"(mbar), "r"(cnt) : "memory");
}
static __device__ __forceinline__ void mbar_arrive(uint32_t mbar) {
    asm volatile("mbarrier.arrive.shared.b64 _, [%0];" :: "r"(mbar) : "memory");
}
static __device__ __forceinline__ void mbar_wait(uint32_t mbar, uint32_t parity) {
    asm volatile(
        "{.reg .pred P;\n"
        "W_%=:\n"
        "mbarrier.try_wait.parity.acquire.cta.shared::cta.b64 P, [%0], %1, 0x989680;\n"
        "@!P bra W_%=;}\n" :: "r"(mbar), "r"(parity) : "memory");
}
static __device__ __forceinline__ void tmem_alloc(uint32_t smem_dst, uint32_t ncols) {
    asm volatile("tcgen05.alloc.cta_group::1.sync.aligned.shared::cta.b32 [%0], %1;"
                 :: "r"(smem_dst), "r"(ncols) : "memory");
}
static __device__ __forceinline__ void tmem_dealloc(uint32_t tmem, uint32_t ncols) {
    asm volatile("tcgen05.relinquish_alloc_permit.cta_group::1.sync.aligned;");
    asm volatile("tcgen05.dealloc.cta_group::1.sync.aligned.b32 %0, %1;" :: "r"(tmem), "r"(ncols));
}
static __device__ __forceinline__ void mma_f16_ss(uint32_t d, uint64_t a, uint64_t b, uint32_t acc) {
    asm volatile(
        "{.reg .pred p; setp.ne.u32 p, %4, 0;\n"
        "tcgen05.mma.cta_group::1.kind::f16 [%0], %1, %2, %3, {%5,%5,%5,%5}, p;}\n"
        :: "r"(d), "l"(a), "l"(b), "r"(IDESC), "r"(acc), "r"(0u) : "memory");
}
static __device__ __forceinline__ void mma_commit(uint32_t mbar) {
    asm volatile(
        "tcgen05.commit.cta_group::1.mbarrier::arrive::one.shared::cluster.b64 [%0];"
        :: "r"(mbar) : "memory");
}
static __device__ __forceinline__ uint32_t elect_one() {
    uint32_t p;
    asm volatile("{.reg .pred P; elect.sync _|P, 0xFFFFFFFF; selp.b32 %0, 1, 0, P;}" : "=r"(p));
    return p;
}
static __device__ __forceinline__ void ldtm32(uint32_t* r, uint32_t a) {
    asm volatile(
        "tcgen05.ld.sync.aligned.32x32b.x32.b32 "
        "{%0,%1,%2,%3,%4,%5,%6,%7,%8,%9,%10,%11,%12,%13,%14,%15,"
        "%16,%17,%18,%19,%20,%21,%22,%23,%24,%25,%26,%27,%28,%29,%30,%31}, [%32];"
        : "=r"(r[0]), "=r"(r[1]), "=r"(r[2]), "=r"(r[3]), "=r"(r[4]), "=r"(r[5]),
          "=r"(r[6]), "=r"(r[7]), "=r"(r[8]), "=r"(r[9]), "=r"(r[10]), "=r"(r[11]),
          "=r"(r[12]), "=r"(r[13]), "=r"(r[14]), "=r"(r[15]), "=r"(r[16]), "=r"(r[17]),
          "=r"(r[18]), "=r"(r[19]), "=r"(r[20]), "=r"(r[21]), "=r"(r[22]), "=r"(r[23]),
          "=r"(r[24]), "=r"(r[25]), "=r"(r[26]), "=r"(r[27]), "=r"(r[28]), "=r"(r[29]),
          "=r"(r[30]), "=r"(r[31])
        : "r"(a));
}
#endif  // TCPATH

// prep: zero stats + convert W -> blocked-atom SW128 bf16 hi/lo chunk tiles.
// Chunk tile: 64 expert rows x 128 k (bf16) = 16KB; atom = 8 rows x 128B;
// atom_col = k/64, atom stride within col = 1024B, col stride = 8*1024B.
__global__ void router_wprep(const float* __restrict__ W) {
    const int c = blockIdx.x;
    const int tid = threadIdx.x;
    if (c == 0) {
        if (tid < NEXP) { g_counts[tid] = 0.f; g_sumprobs[tid] = 0.f; }
        if (tid == 0) g_entropy = 0.f;
    }
    const int e  = tid >> 2;           // expert row 0..63
    const int kq = (tid & 3) * 32;     // k offset within chunk (32 fp32 = 8 float4)
    const float* wp = W + (size_t)e * HID + c * KC + kq;
#pragma unroll
    for (int j = 0; j < 8; j++) {
        const int k = kq + 4 * j;
        float4 v = *(const float4*)(wp + 4 * j);
        uint2 hi, lo;
        split4(v, hi, lo);
        uint32_t base = (uint32_t)(((e >> 3) + (k >> 6) * 8) * 1024 + (e & 7) * 128 + (k & 63) * 2);
        uint32_t off = c * 16384 + swz(base);
        *(uint2*)(g_wh + off) = hi;
        *(uint2*)(g_wl + off) = lo;
    }
}

__global__ __launch_bounds__(288, 1)
void router_main(const float* __restrict__ x, const float* __restrict__ W,
                 float* __restrict__ out) {
    extern __shared__ char sm[];
    const uint32_t smb = s2u(sm);
    const int tid = threadIdx.x;
    const int lane = tid & 31;
    const int t0 = blockIdx.x * TM;

    float l[64];

#if TCPATH
    // ======================= tcgen05 path: 2-stage ring, KC=128 =======================
    if (tid == 0) {
#pragma unroll
        for (int s = 0; s < NSTAGE; s++) {
            mbar_init(smb + MB_FULL(s), 1);     // tid0 arrives for all producers
            mbar_init(smb + MB_EMPTY(s), 1);    // mma commit
        }
    }
    if ((tid >> 5) == 0) tmem_alloc(smb + SMEM_TMEM_PTR, 64);
    __syncthreads();
    uint32_t tmem;
    asm volatile("ld.shared.b32 %0, [%1];" : "=r"(tmem) : "r"(smb + SMEM_TMEM_PTR));

    if (tid < 256) {
        // ---- producers: warps 0-7. x convert + W raw copy, 1-deep prefetch ----
        const int qp = tid & 15;       // k-octet: k0 = 8*qp (8 fp32)
        const int tb = tid >> 4;       // row base 0..15; rows tb + 16r
        const float* xp = x + (size_t)(t0 + tb) * HID + qp * 8;
        // x smem address (constant part): row = tb+16r -> atom_row = (tb>>3)+2r
        const uint32_t xbase0 = (uint32_t)((((tb >> 3) + (qp >> 3) * 16) * 1024)
                                           + (tb & 7) * 128 + (qp & 7) * 16);

        float4 xa[8], xb[8];
#pragma unroll
        for (int r = 0; r < 8; r++) {
            xa[r] = *(const float4*)(xp + (size_t)r * 16 * HID);
            xb[r] = *(const float4*)(xp + (size_t)r * 16 * HID + 4);
        }

#pragma unroll 1
        for (int c = 0; c < NCHUNK; c++) {
            const int s = c & 1;
            const uint32_t st = STAGE_BASE + s * STAGE_SZ;
            if (lane == 0) mbar_wait(smb + MB_EMPTY(s), 1u ^ ((c >> 1) & 1));
            __syncwarp();

            // x: 8 row-pairs -> uint4 hi + uint4 lo each
#pragma unroll
            for (int r = 0; r < 8; r++) {
                uint2 h0, l0, h1, l1;
                split4(xa[r], h0, l0);
                split4(xb[r], h1, l1);
                uint32_t off = swz(xbase0 + (uint32_t)(2 * r) * 1024);
                *(uint4*)(sm + st + XH_OFF + off) = make_uint4(h0.x, h0.y, h1.x, h1.y);
                *(uint4*)(sm + st + XL_OFF + off) = make_uint4(l0.x, l0.y, l1.x, l1.y);
            }
            // W: raw copy of pre-swizzled tiles (16KB hi + 16KB lo), 4 uint4 each
#pragma unroll
            for (int i = 0; i < 4; i++) {
                const uint32_t wo = (uint32_t)(tid + 256 * i) * 16;
                *(uint4*)(sm + st + WH_OFF + wo) =
                    *(const uint4*)(g_wh + (size_t)c * 16384 + wo);
                *(uint4*)(sm + st + WL_OFF + wo) =
                    *(const uint4*)(g_wl + (size_t)c * 16384 + wo);
            }
            // prefetch next chunk's x
            if (c + 1 < NCHUNK) {
                const int k0 = (c + 1) * KC;
#pragma unroll
                for (int r = 0; r < 8; r++) {
                    xa[r] = *(const float4*)(xp + k0 + (size_t)r * 16 * HID);
                    xb[r] = *(const float4*)(xp + k0 + (size_t)r * 16 * HID + 4);
                }
            }
            asm volatile("bar.sync 1, 256;" ::: "memory");
            if (tid == 0) {
                asm volatile("fence.proxy.async.shared::cta;" ::: "memory");
                mbar_arrive(smb + MB_FULL(s));
            }
        }
    } else {
        // ---- warp 8: pure MMA pacer ----
        const uint32_t one = elect_one();
#pragma unroll 1
        for (int c = 0; c < NCHUNK; c++) {
            const int s = c & 1;
            const uint32_t st = STAGE_BASE + s * STAGE_SZ;
            mbar_wait(smb + MB_FULL(s), (c >> 1) & 1);
            if (one) {
                uint64_t axh = mk_desc(smb + st + XH_OFF);
                uint64_t axl = mk_desc(smb + st + XL_OFF);
                uint64_t bwh = mk_desc(smb + st + WH_OFF);
                uint64_t bwl = mk_desc(smb + st + WL_OFF);
                // k-step desc offsets: x atom_col 1 at +1024 units, W at +512
#pragma unroll
                for (int k = 0; k < 8; k++) {
                    uint64_t xo = (uint64_t)((k & 3) * 2 + (k >> 2) * 1024);
                    uint64_t wo = (uint64_t)((k & 3) * 2 + (k >> 2) * 512);
                    mma_f16_ss(tmem, axh + xo, bwh + wo, (c > 0) | (k > 0));
                }
#pragma unroll
                for (int k = 0; k < 8; k++) {
                    uint64_t xo = (uint64_t)((k & 3) * 2 + (k >> 2) * 1024);
                    uint64_t wo = (uint64_t)((k & 3) * 2 + (k >> 2) * 512);
                    mma_f16_ss(tmem, axh + xo, bwl + wo, 1);
                }
#pragma unroll
                for (int k = 0; k < 8; k++) {
                    uint64_t xo = (uint64_t)((k & 3) * 2 + (k >> 2) * 1024);
                    uint64_t wo = (uint64_t)((k & 3) * 2 + (k >> 2) * 512);
                    mma_f16_ss(tmem, axl + xo, bwh + wo, 1);
                }
                mma_commit(smb + MB_EMPTY(s));
            }
        }
    }

    // drain: each empty barrier completes 16 times (32 chunks / 2 stages);
    // waiting parity 1 here = the 16th (final) completion, as in prior rounds.
    __syncthreads();
#pragma unroll
    for (int s = 0; s < NSTAGE; s++) mbar_wait(smb + MB_EMPTY(s), 1);
    asm volatile("tcgen05.fence::after_thread_sync;" ::: "memory");

    if (tid < 128) {
        ldtm32((uint32_t*)l, tmem);
        ldtm32((uint32_t*)l + 32, tmem + 32);
        asm volatile("tcgen05.wait::ld.sync.aligned;" ::: "memory");
    }
#else
    // ======================= fp32 SIMT fallback (KC=64 chunks) =======================
    float* x_s = (float*)(sm + FB_X);
    float* w_s = (float*)(sm + FB_W);
    float* l_s = (float*)(sm + FB_L);
    const int q  = tid & 15;
    const int tb = tid >> 4;
    const int tx = tid & 15;
    const int ty = (tid >> 4) & 15;
    const float* xp = x + (size_t)(t0 + (tb & 15)) * HID + q * 4;
    const float* wp = W + (size_t)(tb & 15) * HID + q * 4;

    float acc[8][4];
#pragma unroll
    for (int i = 0; i < 8; i++)
#pragma unroll
        for (int j = 0; j < 4; j++) acc[i][j] = 0.f;

    float4 xr[8], wr[4];
    if (tid < 256) {
#pragma unroll
        for (int r = 0; r < 8; r++) xr[r] = *(const float4*)(xp + (size_t)r * 16 * HID);
#pragma unroll
        for (int p = 0; p < 4; p++) wr[p] = *(const float4*)(wp + (size_t)p * 16 * HID);
    }

#pragma unroll 1
    for (int c = 0; c < 64; c++) {
        if (tid < 256) {
#pragma unroll
            for (int r = 0; r < 8; r++) {
                const float v[4] = {xr[r].x, xr[r].y, xr[r].z, xr[r].w};
#pragma unroll
                for (int j = 0; j < 4; j++) x_s[(q * 4 + j) * (TM + 1) + (tb & 15) + 16 * r] = v[j];
            }
#pragma unroll
            for (int p = 0; p < 4; p++) {
                const float v[4] = {wr[p].x, wr[p].y, wr[p].z, wr[p].w};
#pragma unroll
                for (int j = 0; j < 4; j++) w_s[(q * 4 + j) * (NEXP + 1) + (tb & 15) + 16 * p] = v[j];
            }
        }
        __syncthreads();
        if (tid < 256) {
            if (c + 1 < 64) {
                const int k0 = (c + 1) * 64;
#pragma unroll
                for (int r = 0; r < 8; r++) xr[r] = *(const float4*)(xp + k0 + (size_t)r * 16 * HID);
#pragma unroll
                for (int p = 0; p < 4; p++) wr[p] = *(const float4*)(wp + k0 + (size_t)p * 16 * HID);
            }
#pragma unroll 8
            for (int kk = 0; kk < 64; kk++) {
                float xf[8], wf[4];
#pragma unroll
                for (int i = 0; i < 8; i++) xf[i] = x_s[kk * (TM + 1) + tx + 16 * i];
#pragma unroll
                for (int j = 0; j < 4; j++) wf[j] = w_s[kk * (NEXP + 1) + ty + 16 * j];
#pragma unroll
                for (int i = 0; i < 8; i++)
#pragma unroll
                    for (int j = 0; j < 4; j++) acc[i][j] = fmaf(xf[i], wf[j], acc[i][j]);
            }
        }
        __syncthreads();
    }
    if (tid < 256) {
#pragma unroll
        for (int i = 0; i < 8; i++)
#pragma unroll
            for (int j = 0; j < 4; j++)
                l_s[(tx + 16 * i) * (NEXP + 1) + ty + 16 * j] = acc[i][j];
    }
    __syncthreads();
    if (tid < 128) {
#pragma unroll
        for (int e = 0; e < NEXP; e++) l[e] = l_s[tid * (NEXP + 1) + e];
    }
#endif

    // ======================= common epilogue =======================
    if (tid < 128) {
        float m = -1e30f, v1 = -1e30f, v2 = -1e30f;
        int i1 = 0, i2 = 0;
#pragma unroll
        for (int e = 0; e < NEXP; e++) {
            float v = l[e];
            m = fmaxf(m, v);
            if (v > v1)      { v2 = v1; i2 = i1; v1 = v; i1 = e; }
            else if (v > v2) { v2 = v;  i2 = e; }
        }
        float s = 0.f, A = 0.f;
#pragma unroll
        for (int e = 0; e < NEXP; e++) {
            float d = l[e] - m;
            float p = __expf(d);
            l[e] = p;
            s += p;
            A = fmaf(d, p, A);
        }
        const float inv = 1.0f / s;

        const float p1 = __expf(v1 - m), p2 = __expf(v2 - m);
        const float iw = 1.0f / (p1 + p2);
        const int token = t0 + tid;
        out[2 * token]                = (float)i1;
        out[2 * token + 1]            = (float)i2;
        out[2 * NTOK + 2 * token]     = p1 * iw;
        out[2 * NTOK + 2 * token + 1] = p2 * iw;
        atomicAdd(&g_counts[i1], 1.0f);
        atomicAdd(&g_counts[i2], 1.0f);

        float ent = __logf(s) - A * inv;
#pragma unroll
        for (int o = 16; o > 0; o >>= 1) ent += __shfl_xor_sync(0xffffffffu, ent, o);
        if (lane == 0) atomicAdd(&g_entropy, ent);

        float* pn = (float*)(sm + PN_OFF) + tid * PN_STRIDE;
#pragma unroll
        for (int e4 = 0; e4 < 16; e4++) {
            float4 v;
            v.x = l[4 * e4 + 0] * inv;
            v.y = l[4 * e4 + 1] * inv;
            v.z = l[4 * e4 + 2] * inv;
            v.w = l[4 * e4 + 3] * inv;
            *(float4*)(pn + 4 * e4) = v;
        }
    }
    __syncthreads();

    if (tid < 256) {
        const int e = tid & 63;
        const int g = tid >> 6;
        const float* pn = (float*)(sm + PN_OFF);
        float ps = 0.f;
#pragma unroll 8
        for (int t = g * 32; t < g * 32 + 32; t++)
            ps += pn[t * PN_STRIDE + e];
        atomicAdd(&g_sumprobs[e], ps);
    }
#if TCPATH
    __syncthreads();
    if ((tid >> 5) == 0) tmem_dealloc(tmem, 64);
#endif
}

__global__ void router_finalize(float* __restrict__ out) {
    int tid = threadIdx.x;
    if (tid < NEXP) {
        out[2 * NTOK * 2 + tid]        = g_counts[tid];
        out[2 * NTOK * 2 + NEXP + tid] = g_sumprobs[tid] * (1.0f / (float)NTOK);
    }
    __syncthreads();
    if (tid == 0) {
        out[2 * NTOK * 2 + 2 * NEXP] = g_entropy * (1.0f / (float)NTOK);
        float c[NEXP];
        for (int i = 0; i < NEXP; i++) c[i] = g_counts[i];
        for (int i = 1; i < NEXP; i++) {
            float v = c[i]; int j = i - 1;
            while (j >= 0 && c[j] > v) { c[j + 1] = c[j]; j--; }
            c[j + 1] = v;
        }
        float num = 0.f, tot = 0.f;
        for (int i = 0; i < NEXP; i++) {
            num = fmaf(2.0f * (float)(i + 1) - (float)NEXP - 1.0f, c[i], num);
            tot += c[i];
        }
        out[2 * NTOK * 2 + 2 * NEXP + 1] = num / ((float)NEXP * tot + 1e-10f);
    }
}

extern "C" void kernel_launch(void* const* d_in, const int* in_sizes, int n_in,
                              void* d_out, int out_size) {
    const float* x = (const float*)d_in[0];
    const float* W = (const float*)d_in[1];
    float* out = (float*)d_out;

    cudaFuncSetAttribute(router_main, cudaFuncAttributeMaxDynamicSharedMemorySize, SMEM_BYTES);

    router_wprep<<<NCHUNK, 256>>>(W);
    router_main<<<NCTA, 288, SMEM_BYTES>>>(x, W, out);
    router_finalize<<<1, 64>>>(out);
}